// round 1
// baseline (speedup 1.0000x reference)
#include <cuda_runtime.h>

// 2D single-level DWT (L=2 filters, e.g. Haar), symmetric pad + odd-phase
// downsample reduces to a pure 2x2 stencil per output group.
// Input : x[b][r][c], b<64, r,c<512  (f32)
// Output: out[b][.][.] 512x512 per image, quadrants [[ll, hl],[lh, hh]]
//
// Each thread handles TWO adjacent 2x2 input blocks:
//   loads : 2x float4 (rows 2n and 2n+1, cols 4t..4t+3)  -- coalesced
//   stores: 4x float2 (one per quadrant)                 -- coalesced

__global__ void __launch_bounds__(256) dwt_haar_kernel(
    const float* __restrict__ x,
    const float* __restrict__ lpf,
    const float* __restrict__ hpf,
    float* __restrict__ out)
{
    // thread decomposition: t in [0,128) covers 2 output cols, n in [0,256), b in [0,64)
    const int gid = blockIdx.x * blockDim.x + threadIdx.x;
    const int t = gid & 127;          // width-pair index
    const int n = (gid >> 7) & 255;   // output row within subband
    const int b = gid >> 15;          // batch

    const float lo0 = __ldg(&lpf[0]);
    const float lo1 = __ldg(&lpf[1]);
    const float hi0 = __ldg(&hpf[0]);
    const float hi1 = __ldg(&hpf[1]);

    const long long img_in  = (long long)b * (512 * 512);
    const long long row0    = img_in + (long long)(2 * n) * 512 + 4 * t;
    const long long row1    = row0 + 512;

    const float4 r0 = *reinterpret_cast<const float4*>(x + row0);
    const float4 r1 = *reinterpret_cast<const float4*>(x + row1);

    // block 0: (r0.x, r0.y / r1.x, r1.y), block 1: (r0.z, r0.w / r1.z, r1.w)
    float2 ll, lh, hl, hh;
    {
        float a_top = lo0 * r0.x + lo1 * r0.y;
        float a_bot = lo0 * r1.x + lo1 * r1.y;
        float d_top = hi0 * r0.x + hi1 * r0.y;
        float d_bot = hi0 * r1.x + hi1 * r1.y;
        ll.x = lo0 * a_top + lo1 * a_bot;
        lh.x = hi0 * a_top + hi1 * a_bot;
        hl.x = lo0 * d_top + lo1 * d_bot;
        hh.x = hi0 * d_top + hi1 * d_bot;
    }
    {
        float a_top = lo0 * r0.z + lo1 * r0.w;
        float a_bot = lo0 * r1.z + lo1 * r1.w;
        float d_top = hi0 * r0.z + hi1 * r0.w;
        float d_bot = hi0 * r1.z + hi1 * r1.w;
        ll.y = lo0 * a_top + lo1 * a_bot;
        lh.y = hi0 * a_top + hi1 * a_bot;
        hl.y = lo0 * d_top + lo1 * d_bot;
        hh.y = hi0 * d_top + hi1 * d_bot;
    }

    const long long img_out = (long long)b * (512 * 512);
    const int m = 2 * t;  // output col within subband (even)
    float* o_ll = out + img_out + (long long)n * 512 + m;
    float* o_lh = out + img_out + (long long)(n + 256) * 512 + m;
    float* o_hl = o_ll + 256;
    float* o_hh = o_lh + 256;

    *reinterpret_cast<float2*>(o_ll) = ll;
    *reinterpret_cast<float2*>(o_lh) = lh;
    *reinterpret_cast<float2*>(o_hl) = hl;
    *reinterpret_cast<float2*>(o_hh) = hh;
}

extern "C" void kernel_launch(void* const* d_in, const int* in_sizes, int n_in,
                              void* d_out, int out_size)
{
    const float* x   = (const float*)d_in[0];
    const float* lpf = (const float*)d_in[1];
    const float* hpf = (const float*)d_in[2];
    float* out = (float*)d_out;

    // 64 * 256 * 128 threads total
    const int total = 64 * 256 * 128;
    dwt_haar_kernel<<<total / 256, 256>>>(x, lpf, hpf, out);
}

// round 2
// speedup vs baseline: 1.0014x; 1.0014x over previous
#include <cuda_runtime.h>

// 2D single-level DWT (L=2, Haar-style), symmetric pad + odd-phase downsample
// reduces to a pure 2x2 stencil per output group.
// Input : x[b][r][c], b<64, r,c<512 (f32)
// Output: 512x512 per image, quadrants [[ll, hl],[lh, hh]]
//
// Each thread: 8 input cols x 2 rows (4x float4 loads, front-batched for MLP),
// stores one float4 per quadrant (4x STG.128, fully coalesced).

__global__ void __launch_bounds__(256) dwt_haar_kernel(
    const float* __restrict__ x,
    const float* __restrict__ lpf,
    const float* __restrict__ hpf,
    float* __restrict__ out)
{
    // t in [0,64): covers input cols 8t..8t+7 (4 output cols per quadrant)
    // n in [0,256): output row within subband
    // b in [0,64): batch
    const int gid = blockIdx.x * blockDim.x + threadIdx.x;
    const int t = gid & 63;
    const int n = (gid >> 6) & 255;
    const int b = gid >> 14;

    const long long img  = (long long)b * (512 * 512);
    const float* p0 = x + img + (long long)(2 * n) * 512 + 8 * t;
    const float* p1 = p0 + 512;

    // 4 independent loads, issued back-to-back (MLP=4)
    const float4 r0a = *reinterpret_cast<const float4*>(p0);
    const float4 r0b = *reinterpret_cast<const float4*>(p0 + 4);
    const float4 r1a = *reinterpret_cast<const float4*>(p1);
    const float4 r1b = *reinterpret_cast<const float4*>(p1 + 4);

    const float lo0 = __ldg(&lpf[0]);
    const float lo1 = __ldg(&lpf[1]);
    const float hi0 = __ldg(&hpf[0]);
    const float hi1 = __ldg(&hpf[1]);

    float4 ll, lh, hl, hh;

    {   // block 0: cols (0,1)
        float at = lo0 * r0a.x + lo1 * r0a.y, ab = lo0 * r1a.x + lo1 * r1a.y;
        float dt = hi0 * r0a.x + hi1 * r0a.y, db = hi0 * r1a.x + hi1 * r1a.y;
        ll.x = lo0 * at + lo1 * ab;  lh.x = hi0 * at + hi1 * ab;
        hl.x = lo0 * dt + lo1 * db;  hh.x = hi0 * dt + hi1 * db;
    }
    {   // block 1: cols (2,3)
        float at = lo0 * r0a.z + lo1 * r0a.w, ab = lo0 * r1a.z + lo1 * r1a.w;
        float dt = hi0 * r0a.z + hi1 * r0a.w, db = hi0 * r1a.z + hi1 * r1a.w;
        ll.y = lo0 * at + lo1 * ab;  lh.y = hi0 * at + hi1 * ab;
        hl.y = lo0 * dt + lo1 * db;  hh.y = hi0 * dt + hi1 * db;
    }
    {   // block 2: cols (4,5)
        float at = lo0 * r0b.x + lo1 * r0b.y, ab = lo0 * r1b.x + lo1 * r1b.y;
        float dt = hi0 * r0b.x + hi1 * r0b.y, db = hi0 * r1b.x + hi1 * r1b.y;
        ll.z = lo0 * at + lo1 * ab;  lh.z = hi0 * at + hi1 * ab;
        hl.z = lo0 * dt + lo1 * db;  hh.z = hi0 * dt + hi1 * db;
    }
    {   // block 3: cols (6,7)
        float at = lo0 * r0b.z + lo1 * r0b.w, ab = lo0 * r1b.z + lo1 * r1b.w;
        float dt = hi0 * r0b.z + hi1 * r0b.w, db = hi0 * r1b.z + hi1 * r1b.w;
        ll.w = lo0 * at + lo1 * ab;  lh.w = hi0 * at + hi1 * ab;
        hl.w = lo0 * dt + lo1 * db;  hh.w = hi0 * dt + hi1 * db;
    }

    const int m = 4 * t;  // output col within subband
    float* o_ll = out + img + (long long)n * 512 + m;
    float* o_lh = out + img + (long long)(n + 256) * 512 + m;

    *reinterpret_cast<float4*>(o_ll)       = ll;
    *reinterpret_cast<float4*>(o_ll + 256) = hl;
    *reinterpret_cast<float4*>(o_lh)       = lh;
    *reinterpret_cast<float4*>(o_lh + 256) = hh;
}

extern "C" void kernel_launch(void* const* d_in, const int* in_sizes, int n_in,
                              void* d_out, int out_size)
{
    const float* x   = (const float*)d_in[0];
    const float* lpf = (const float*)d_in[1];
    const float* hpf = (const float*)d_in[2];
    float* out = (float*)d_out;

    // 64 batches * 256 row-pairs * 64 col-groups = 1,048,576 threads
    const int total = 64 * 256 * 64;
    dwt_haar_kernel<<<total / 256, 256>>>(x, lpf, hpf, out);
}

// round 3
// speedup vs baseline: 1.0678x; 1.0663x over previous
#include <cuda_runtime.h>

// 2D single-level DWT (L=2, Haar-style): symmetric pad + odd-phase downsample
// reduces to a pure 2x2 stencil per output group.
// Input : x[b][r][c], b<64, r,c<512 (f32) -> 64 MB, fits (mostly) in 126 MB L2
// Output: 512x512 per image, quadrants [[ll, hl],[lh, hh]]
//
// R1 mapping (2x float4 loads, 4x float2 stores per thread) was the fastest;
// R3 change: output stores use __stcs (evict-first) so the 64 MB output stream
// does not thrash the L2-resident input across graph replays.

__global__ void __launch_bounds__(256) dwt_haar_kernel(
    const float* __restrict__ x,
    const float* __restrict__ lpf,
    const float* __restrict__ hpf,
    float* __restrict__ out)
{
    // t in [0,128): width-pair index, n in [0,256): subband row, b: batch
    const int gid = blockIdx.x * blockDim.x + threadIdx.x;
    const int t = gid & 127;
    const int n = (gid >> 7) & 255;
    const int b = gid >> 15;

    const long long img = (long long)b * (512 * 512);
    const float* p0 = x + img + (long long)(2 * n) * 512 + 4 * t;

    const float4 r0 = *reinterpret_cast<const float4*>(p0);
    const float4 r1 = *reinterpret_cast<const float4*>(p0 + 512);

    const float lo0 = __ldg(&lpf[0]);
    const float lo1 = __ldg(&lpf[1]);
    const float hi0 = __ldg(&hpf[0]);
    const float hi1 = __ldg(&hpf[1]);

    float2 ll, lh, hl, hh;
    {
        float at = lo0 * r0.x + lo1 * r0.y, ab = lo0 * r1.x + lo1 * r1.y;
        float dt = hi0 * r0.x + hi1 * r0.y, db = hi0 * r1.x + hi1 * r1.y;
        ll.x = lo0 * at + lo1 * ab;  lh.x = hi0 * at + hi1 * ab;
        hl.x = lo0 * dt + lo1 * db;  hh.x = hi0 * dt + hi1 * db;
    }
    {
        float at = lo0 * r0.z + lo1 * r0.w, ab = lo0 * r1.z + lo1 * r1.w;
        float dt = hi0 * r0.z + hi1 * r0.w, db = hi0 * r1.z + hi1 * r1.w;
        ll.y = lo0 * at + lo1 * ab;  lh.y = hi0 * at + hi1 * ab;
        hl.y = lo0 * dt + lo1 * db;  hh.y = hi0 * dt + hi1 * db;
    }

    const int m = 2 * t;
    float* o_ll = out + img + (long long)n * 512 + m;
    float* o_lh = out + img + (long long)(n + 256) * 512 + m;

    // Evict-first stores: keep the input resident in L2 across graph replays.
    __stcs(reinterpret_cast<float2*>(o_ll),       ll);
    __stcs(reinterpret_cast<float2*>(o_ll + 256), hl);
    __stcs(reinterpret_cast<float2*>(o_lh),       lh);
    __stcs(reinterpret_cast<float2*>(o_lh + 256), hh);
}

extern "C" void kernel_launch(void* const* d_in, const int* in_sizes, int n_in,
                              void* d_out, int out_size)
{
    const float* x   = (const float*)d_in[0];
    const float* lpf = (const float*)d_in[1];
    const float* hpf = (const float*)d_in[2];
    float* out = (float*)d_out;

    const int total = 64 * 256 * 128;  // 2,097,152 threads
    dwt_haar_kernel<<<total / 256, 256>>>(x, lpf, hpf, out);
}